// round 1
// baseline (speedup 1.0000x reference)
#include <cuda_runtime.h>
#include <math.h>

// Problem constants (match reference setup_inputs)
#define NNODES 100000
#define NEDGES 3200000
#define NFEAT  256
#define NHID   128
#define NCLASS 40

// ---------------- scratch (static device globals; no runtime alloc) ----------
__device__ float g_Self[(size_t)NNODES * NHID];   // self-projection / h buffers
__device__ float g_P[(size_t)NNODES * NHID];      // neighbor-projection buffer
__device__ float g_H[(size_t)NNODES * NHID];      // hidden activations
__device__ int   g_deg[NNODES];
__device__ int   g_rowptr[NNODES + 1];
__device__ int   g_cursor[NNODES];
__device__ int   g_colidx[NEDGES];
__device__ float g_invdeg[NNODES];

// ---------------- CSR build ----------------
__global__ void k_zero_deg() {
    int i = blockIdx.x * blockDim.x + threadIdx.x;
    if (i < NNODES) g_deg[i] = 0;
}

__global__ void k_hist(const int* __restrict__ rows, int E) {
    int e = blockIdx.x * blockDim.x + threadIdx.x;
    if (e < E) atomicAdd(&g_deg[rows[e]], 1);
}

// Single-block chunked exclusive scan of g_deg -> g_rowptr
__global__ void k_scan() {
    __shared__ int wsum[32];
    __shared__ int carry_s;
    int tid = threadIdx.x, lane = tid & 31, wid = tid >> 5;
    if (tid == 0) carry_s = 0;
    __syncthreads();
    for (int base = 0; base < NNODES; base += 1024) {
        int i = base + tid;
        int v = (i < NNODES) ? g_deg[i] : 0;
        int x = v;
        #pragma unroll
        for (int o = 1; o < 32; o <<= 1) {
            int t = __shfl_up_sync(0xffffffffu, x, o);
            if (lane >= o) x += t;
        }
        if (lane == 31) wsum[wid] = x;
        __syncthreads();
        if (wid == 0) {
            int y = wsum[lane];
            #pragma unroll
            for (int o = 1; o < 32; o <<= 1) {
                int t = __shfl_up_sync(0xffffffffu, y, o);
                if (lane >= o) y += t;
            }
            wsum[lane] = y;
        }
        __syncthreads();
        int incl = x + (wid > 0 ? wsum[wid - 1] : 0) + carry_s;
        if (i < NNODES) g_rowptr[i] = incl - v;
        __syncthreads();
        if (tid == 1023) carry_s = incl;
        __syncthreads();
    }
    if (threadIdx.x == 0) g_rowptr[NNODES] = carry_s;
}

__global__ void k_aux() {
    int i = blockIdx.x * blockDim.x + threadIdx.x;
    if (i < NNODES) {
        g_cursor[i] = g_rowptr[i];
        g_invdeg[i] = 1.0f / ((float)g_deg[i] + 1.0f);
    }
}

__global__ void k_scatter(const int* __restrict__ rows, const int* __restrict__ cols, int E) {
    int e = blockIdx.x * blockDim.x + threadIdx.x;
    if (e < E) {
        int r = rows[e];
        int p = atomicAdd(&g_cursor[r], 1);
        g_colidx[p] = cols[e];
    }
}

// ---------------- SGEMM: C = A[N x K] * B^T  (B rows come from two slabs) ---
// Row m of B: m < Msplit -> B0 + m*ldb ; else -> B1 + (m-Msplit)*ldb.
// Output: col m < Msplit -> C0[row*ldc + m] ; else -> C1[row*ldc + (m-Msplit)].
__global__ __launch_bounds__(256, 2) void sgemm_kernel(
    const float* __restrict__ A,
    const float* __restrict__ B0, const float* __restrict__ B1,
    int K, int ldb, int Msplit, int M,
    float* __restrict__ C0, float* __restrict__ C1,
    int ldc, int Nrows)
{
    __shared__ float As[8][128];
    __shared__ float Bs[8][128];

    int tid = threadIdx.x;
    int n0 = blockIdx.x * 128;
    int m0 = blockIdx.y * 128;
    int tx = tid & 15, ty = tid >> 4;

    float acc[8][8];
    #pragma unroll
    for (int i = 0; i < 8; i++)
        #pragma unroll
        for (int j = 0; j < 8; j++) acc[i][j] = 0.f;

    int aRow = tid >> 1;
    int aCol = (tid & 1) * 4;
    bool aValid = (n0 + aRow) < Nrows;
    const float* Aptr = A + (size_t)(n0 + aRow) * K + aCol;

    int bRow = tid >> 1;
    int bCol = (tid & 1) * 4;
    int m = m0 + bRow;
    const float* Bptr = nullptr;
    if (m < M)
        Bptr = (m < Msplit ? B0 + (size_t)m * ldb
                           : B1 + (size_t)(m - Msplit) * ldb) + bCol;

    for (int k0 = 0; k0 < K; k0 += 8) {
        float4 av = aValid ? *reinterpret_cast<const float4*>(Aptr + k0)
                           : make_float4(0.f, 0.f, 0.f, 0.f);
        float4 bv = Bptr ? *reinterpret_cast<const float4*>(Bptr + k0)
                         : make_float4(0.f, 0.f, 0.f, 0.f);
        As[aCol + 0][aRow] = av.x; As[aCol + 1][aRow] = av.y;
        As[aCol + 2][aRow] = av.z; As[aCol + 3][aRow] = av.w;
        Bs[bCol + 0][bRow] = bv.x; Bs[bCol + 1][bRow] = bv.y;
        Bs[bCol + 2][bRow] = bv.z; Bs[bCol + 3][bRow] = bv.w;
        __syncthreads();

        #pragma unroll
        for (int k = 0; k < 8; k++) {
            float a[8], b[8];
            *reinterpret_cast<float4*>(a)     = *reinterpret_cast<float4*>(&As[k][ty * 8]);
            *reinterpret_cast<float4*>(a + 4) = *reinterpret_cast<float4*>(&As[k][ty * 8 + 4]);
            *reinterpret_cast<float4*>(b)     = *reinterpret_cast<float4*>(&Bs[k][tx * 8]);
            *reinterpret_cast<float4*>(b + 4) = *reinterpret_cast<float4*>(&Bs[k][tx * 8 + 4]);
            #pragma unroll
            for (int i = 0; i < 8; i++)
                #pragma unroll
                for (int j = 0; j < 8; j++)
                    acc[i][j] = fmaf(a[i], b[j], acc[i][j]);
        }
        __syncthreads();
    }

    #pragma unroll
    for (int i = 0; i < 8; i++) {
        int row = n0 + ty * 8 + i;
        if (row >= Nrows) continue;
        #pragma unroll
        for (int j = 0; j < 8; j++) {
            int mm = m0 + tx * 8 + j;
            if (mm >= M) continue;
            if (mm < Msplit) C0[(size_t)row * ldc + mm] = acc[i][j];
            else             C1[(size_t)row * ldc + (mm - Msplit)] = acc[i][j];
        }
    }
}

// ---------------- CSR SpMM fused with SAGE epilogue ----------------
// H[r] = relu(Self[r] + (sum_{c in N(r)} P[c]) * invdeg[r]) ; 128-dim rows.
__global__ void spmm_relu_kernel(const float* __restrict__ P,
                                 const float* __restrict__ S,
                                 float* __restrict__ H)
{
    int warp = (blockIdx.x * blockDim.x + threadIdx.x) >> 5;
    int lane = threadIdx.x & 31;
    if (warp >= NNODES) return;
    int r = warp;
    int start = g_rowptr[r], end = g_rowptr[r + 1];

    float4 acc = make_float4(0.f, 0.f, 0.f, 0.f);
    for (int base = start; base < end; base += 32) {
        int idx = base + lane;
        int c = (idx < end) ? g_colidx[idx] : 0;
        int cnt = min(32, end - base);
        #pragma unroll 4
        for (int j = 0; j < cnt; j++) {
            int cj = __shfl_sync(0xffffffffu, c, j);
            float4 v = *reinterpret_cast<const float4*>(P + (size_t)cj * 128 + lane * 4);
            acc.x += v.x; acc.y += v.y; acc.z += v.z; acc.w += v.w;
        }
    }
    float inv = g_invdeg[r];
    float4 s = *reinterpret_cast<const float4*>(S + (size_t)r * 128 + lane * 4);
    float4 h;
    h.x = fmaxf(fmaf(acc.x, inv, s.x), 0.f);
    h.y = fmaxf(fmaf(acc.y, inv, s.y), 0.f);
    h.z = fmaxf(fmaf(acc.z, inv, s.z), 0.f);
    h.w = fmaxf(fmaf(acc.w, inv, s.w), 0.f);
    *reinterpret_cast<float4*>(H + (size_t)r * 128 + lane * 4) = h;
}

// ---------------- log_softmax (in place, warp per node, adds bias) ----------
__global__ void logsoftmax_kernel(float* __restrict__ out, const float* __restrict__ bias) {
    int warp = (blockIdx.x * blockDim.x + threadIdx.x) >> 5;
    int lane = threadIdx.x & 31;
    if (warp >= NNODES) return;
    float* row = out + (size_t)warp * NCLASS;
    float a = row[lane] + bias[lane];                 // lanes 0..31 (<40)
    float b2 = (lane < NCLASS - 32) ? row[lane + 32] + bias[lane + 32] : -INFINITY;
    float mx = fmaxf(a, b2);
    #pragma unroll
    for (int o = 16; o > 0; o >>= 1)
        mx = fmaxf(mx, __shfl_xor_sync(0xffffffffu, mx, o));
    float se = __expf(a - mx) + ((lane < NCLASS - 32) ? __expf(b2 - mx) : 0.f);
    #pragma unroll
    for (int o = 16; o > 0; o >>= 1)
        se += __shfl_xor_sync(0xffffffffu, se, o);
    float ls = mx + __logf(se);
    row[lane] = a - ls;
    if (lane < NCLASS - 32) row[lane + 32] = b2 - ls;
}

// ---------------- launch ----------------
extern "C" void kernel_launch(void* const* d_in, const int* in_sizes, int n_in,
                              void* d_out, int out_size) {
    const float* x     = (const float*)d_in[0];   // [N,256]
    const float* W1    = (const float*)d_in[1];   // [128,512]
    const float* W2    = (const float*)d_in[2];   // [128,256]
    const float* mlpW  = (const float*)d_in[3];   // [40,128]
    const float* mlpb  = (const float*)d_in[4];   // [40]
    const int*   erow  = (const int*)d_in[5];     // [E]
    const int*   ecol  = (const int*)d_in[6];     // [E]
    int E = in_sizes[5];
    float* out = (float*)d_out;                   // [N,40]

    float *pSelf, *pP, *pH;
    cudaGetSymbolAddress((void**)&pSelf, g_Self);
    cudaGetSymbolAddress((void**)&pP, g_P);
    cudaGetSymbolAddress((void**)&pH, g_H);

    const int nb_nodes = (NNODES + 255) / 256;
    const int nb_edges = (E + 255) / 256;
    const int nb_warps = (NNODES * 32 + 255) / 256;  // warp-per-node kernels

    // CSR build (reused by both layers)
    k_zero_deg<<<nb_nodes, 256>>>();
    k_hist<<<nb_edges, 256>>>(erow, E);
    k_scan<<<1, 1024>>>();
    k_aux<<<nb_nodes, 256>>>();
    k_scatter<<<nb_edges, 256>>>(erow, ecol, E);

    dim3 g1((NNODES + 127) / 128, 2);
    // Layer 1: x @ [W1_self | W1_neigh]^T  -> Self, P
    sgemm_kernel<<<g1, 256>>>(x, W1, W1 + NFEAT, NFEAT, 2 * NFEAT, NHID, 2 * NHID,
                              pSelf, pP, NHID, NNODES);
    spmm_relu_kernel<<<nb_warps, 256>>>(pP, pSelf, pH);

    // Layer 2: h1 @ [W2_self | W2_neigh]^T -> Self, P
    sgemm_kernel<<<g1, 256>>>(pH, W2, W2 + NHID, NHID, 2 * NHID, NHID, 2 * NHID,
                              pSelf, pP, NHID, NNODES);
    spmm_relu_kernel<<<nb_warps, 256>>>(pP, pSelf, pH);

    // Classifier: h2 @ mlpW^T -> logits (d_out), then log_softmax in place
    dim3 g3((NNODES + 127) / 128, 1);
    sgemm_kernel<<<g3, 256>>>(pH, mlpW, nullptr, NHID, NHID, NCLASS, NCLASS,
                              out, nullptr, NCLASS, NNODES);
    logsoftmax_kernel<<<nb_warps, 256>>>(out, mlpb);
}